// round 3
// baseline (speedup 1.0000x reference)
#include <cuda_runtime.h>
#include <math.h>
#include <stdint.h>

// ---------------- problem constants ----------------
#define NL       2
#define DMODEL   512
#define ED       1024
#define DSTATE   16
#define DCONV    4
#define DTRANK   32
#define INPUT_D  64
#define BSZ      2
#define LSEQ     2048
#define T        (BSZ*LSEQ)          // 4096 tokens

// ---------------- scratch (single device global, no allocs) ----------------
// layout (floats):
//  h      : T*DMODEL            = 2,097,152
//  hn     : T*DMODEL            = 2,097,152
//  xz     : T*2*ED              = 8,388,608
//  xi     : T*ED                = 4,194,304
//  delta  : T*ED                = 4,194,304
//  y      : T*ED                = 4,194,304
//  dbc    : T*64                =   262,144
#define OFF_H     0
#define OFF_HN    (OFF_H  + T*DMODEL)
#define OFF_XZ    (OFF_HN + T*DMODEL)
#define OFF_XI    (OFF_XZ + T*2*ED)
#define OFF_DELTA (OFF_XI + T*ED)
#define OFF_Y     (OFF_DELTA + T*ED)
#define OFF_DBC   (OFF_Y  + T*ED)
#define SCRATCH_FLOATS (OFF_DBC + T*64)

__device__ float g_scratch[SCRATCH_FLOATS];

// ---------------- helpers ----------------
__device__ __forceinline__ float softplus_f(float x) {
    return x > 20.f ? x : log1pf(__expf(x));
}
__device__ __forceinline__ float silu_f(float x) {
    return x / (1.f + __expf(-x));
}

// ---------------- tiled SGEMM: C[M,N] = A[M,K] @ W[N,K]^T (+epilogue) ------
// 128x128 tile, BK=8, 256 threads, 8x8 per-thread microtile.
// Requires M%128==0, N%128==0, K%8==0, rows 16B-aligned (lda%4==0).
template<bool BIAS, bool SOFTPLUS, bool RES>
__global__ __launch_bounds__(256)
void sgemm128(const float* __restrict__ A, int lda,
              const float* __restrict__ W,
              const float* __restrict__ bias,
              const float* res,
              float* C, int N, int K)
{
    __shared__ float As[8][128];
    __shared__ float Ws[8][128];

    const int tid  = threadIdx.x;
    const int m0   = blockIdx.y * 128;
    const int n0   = blockIdx.x * 128;
    const int lrow = tid >> 1;            // 0..127
    const int lcol = (tid & 1) * 4;       // 0 or 4
    const float* Ag = A + (size_t)(m0 + lrow) * lda + lcol;
    const float* Wg = W + (size_t)(n0 + lrow) * K   + lcol;

    const int tx = (tid & 15) * 8;        // n offset within tile
    const int ty = (tid >> 4) * 8;        // m offset within tile

    float acc[8][8];
#pragma unroll
    for (int i = 0; i < 8; i++)
#pragma unroll
        for (int j = 0; j < 8; j++) acc[i][j] = 0.f;

    for (int k0 = 0; k0 < K; k0 += 8) {
        float4 av = *reinterpret_cast<const float4*>(Ag + k0);
        float4 wv = *reinterpret_cast<const float4*>(Wg + k0);
        __syncthreads();
        As[lcol+0][lrow] = av.x; As[lcol+1][lrow] = av.y;
        As[lcol+2][lrow] = av.z; As[lcol+3][lrow] = av.w;
        Ws[lcol+0][lrow] = wv.x; Ws[lcol+1][lrow] = wv.y;
        Ws[lcol+2][lrow] = wv.z; Ws[lcol+3][lrow] = wv.w;
        __syncthreads();
#pragma unroll
        for (int kk = 0; kk < 8; kk++) {
            float4 a0 = *reinterpret_cast<const float4*>(&As[kk][ty]);
            float4 a1 = *reinterpret_cast<const float4*>(&As[kk][ty + 4]);
            float4 b0 = *reinterpret_cast<const float4*>(&Ws[kk][tx]);
            float4 b1 = *reinterpret_cast<const float4*>(&Ws[kk][tx + 4]);
            float a[8] = {a0.x,a0.y,a0.z,a0.w,a1.x,a1.y,a1.z,a1.w};
            float b[8] = {b0.x,b0.y,b0.z,b0.w,b1.x,b1.y,b1.z,b1.w};
#pragma unroll
            for (int i = 0; i < 8; i++)
#pragma unroll
                for (int j = 0; j < 8; j++)
                    acc[i][j] = fmaf(a[i], b[j], acc[i][j]);
        }
    }

#pragma unroll
    for (int i = 0; i < 8; i++) {
        const int m = m0 + ty + i;
#pragma unroll
        for (int j = 0; j < 8; j++) {
            const int n = n0 + tx + j;
            float v = acc[i][j];
            if (BIAS)     v += bias[n];
            if (SOFTPLUS) v  = softplus_f(v);
            if (RES)      v += res[(size_t)m * N + n];
            C[(size_t)m * N + n] = v;
        }
    }
}

// ---------------- x_proj: dbc[T,64] = xi[T,ED] @ xp_w[64,ED]^T ------------
// 64 tokens x 64 outputs per block, chunk K by 64, 256 threads, 4x4 microtile.
__global__ __launch_bounds__(256)
void xproj64(const float* __restrict__ xi, const float* __restrict__ w,
             float* __restrict__ dbc)
{
    __shared__ float xs[64][68];   // [e_local][token]
    __shared__ float ws[64][68];   // [e_local][k]
    const int tid  = threadIdx.x;
    const int t0   = blockIdx.x * 64;
    const int tok0 = (tid >> 4) * 4;
    const int k0   = (tid & 15) * 4;

    float acc[4][4] = {};

    for (int e0 = 0; e0 < ED; e0 += 64) {
        __syncthreads();
#pragma unroll
        for (int i = 0; i < 4; i++) {
            int lin = tid + i * 256;        // 0..1023
            int row = lin >> 4;             // 0..63
            int ev  = (lin & 15) * 4;       // 0..60
            float4 xv = *reinterpret_cast<const float4*>(
                &xi[(size_t)(t0 + row) * ED + e0 + ev]);
            xs[ev+0][row] = xv.x; xs[ev+1][row] = xv.y;
            xs[ev+2][row] = xv.z; xs[ev+3][row] = xv.w;
            float4 wv = *reinterpret_cast<const float4*>(
                &w[(size_t)row * ED + e0 + ev]);
            ws[ev+0][row] = wv.x; ws[ev+1][row] = wv.y;
            ws[ev+2][row] = wv.z; ws[ev+3][row] = wv.w;
        }
        __syncthreads();
#pragma unroll
        for (int ee = 0; ee < 64; ee++) {
            float4 a = *reinterpret_cast<const float4*>(&xs[ee][tok0]);
            float4 b = *reinterpret_cast<const float4*>(&ws[ee][k0]);
            float av[4] = {a.x, a.y, a.z, a.w};
            float bv[4] = {b.x, b.y, b.z, b.w};
#pragma unroll
            for (int i = 0; i < 4; i++)
#pragma unroll
                for (int j = 0; j < 4; j++)
                    acc[i][j] = fmaf(av[i], bv[j], acc[i][j]);
        }
    }
#pragma unroll
    for (int i = 0; i < 4; i++) {
        float4 v = make_float4(acc[i][0], acc[i][1], acc[i][2], acc[i][3]);
        *reinterpret_cast<float4*>(&dbc[(size_t)(t0 + tok0 + i) * 64 + k0]) = v;
    }
}

// ---------------- rmsnorm over DMODEL=512, one block per token ------------
__global__ __launch_bounds__(256)
void rmsnorm_k(const float* __restrict__ h, const float* __restrict__ w,
               float* __restrict__ out)
{
    const int t = blockIdx.x;
    const float* row = h + (size_t)t * DMODEL;
    const int tid = threadIdx.x;
    float v0 = row[tid], v1 = row[tid + 256];
    float ss = v0 * v0 + v1 * v1;
#pragma unroll
    for (int o = 16; o; o >>= 1) ss += __shfl_xor_sync(0xffffffffu, ss, o);
    __shared__ float red[8];
    if ((tid & 31) == 0) red[tid >> 5] = ss;
    __syncthreads();
    float tot = red[0] + red[1] + red[2] + red[3] +
                red[4] + red[5] + red[6] + red[7];
    float scale = rsqrtf(tot * (1.f / DMODEL) + 1e-5f);
    out[(size_t)t * DMODEL + tid]       = v0 * scale * w[tid];
    out[(size_t)t * DMODEL + tid + 256] = v1 * scale * w[tid + 256];
}

// ---------------- depthwise causal conv (k=4) + bias + silu ---------------
// reads xi_raw = xz[:, 0:ED], writes xi[T,ED]
__global__ __launch_bounds__(256)
void conv_silu_k(const float* __restrict__ xz, const float* __restrict__ cw,
                 const float* __restrict__ cb, float* __restrict__ xi)
{
    const int idx = blockIdx.x * 256 + threadIdx.x;   // t*ED + e
    const int e = idx & (ED - 1);
    const int t = idx >> 10;
    const int l = t & (LSEQ - 1);
    const float* base = xz + (size_t)t * (2 * ED) + e;
    float acc = cb[e];
#pragma unroll
    for (int k = 0; k < DCONV; k++) {
        int ll = l - (DCONV - 1) + k;
        if (ll >= 0)
            acc = fmaf(base[(ptrdiff_t)(k - (DCONV - 1)) * (2 * ED)],
                       cw[e * DCONV + k], acc);
    }
    xi[idx] = silu_f(acc);
}

// ---------------- selective scan -------------------------------------------
// 2 channels per warp, 16 lanes per channel (one state n each).
// y[t,e] = (sum_n s_n * C_n + D[e]*xi) * silu(z)
__global__ __launch_bounds__(256)
void scan_k(const float* __restrict__ delta, const float* __restrict__ xi,
            const float* __restrict__ xz, const float* __restrict__ dbc,
            const float* __restrict__ A_log, const float* __restrict__ Dp,
            float* __restrict__ y)
{
    const int gid = blockIdx.x * 256 + threadIdx.x;
    const int c = gid >> 4;           // channel 0..2047 (b*ED + e)
    const int n = gid & 15;
    const int b = c >> 10;
    const int e = c & (ED - 1);

    const float a  = -__expf(A_log[e * DSTATE + n]);
    const float dE = Dp[e];

    float s = 0.f;
    const size_t tb = (size_t)b * LSEQ;
    for (int l = 0; l < LSEQ; l++) {
        const size_t t = tb + l;
        float dv = delta[t * ED + e];
        float xv = xi[t * ED + e];
        float zv = xz[t * (2 * ED) + ED + e];
        float Bv = dbc[t * 64 + DTRANK + n];
        float Cv = dbc[t * 64 + DTRANK + DSTATE + n];
        float dA = __expf(dv * a);
        s = fmaf(dA, s, dv * xv * Bv);
        float p = s * Cv;
        p += __shfl_xor_sync(0xffffffffu, p, 8, 16);
        p += __shfl_xor_sync(0xffffffffu, p, 4, 16);
        p += __shfl_xor_sync(0xffffffffu, p, 2, 16);
        p += __shfl_xor_sync(0xffffffffu, p, 1, 16);
        if (n == 0)
            y[t * ED + e] = (p + dE * xv) * silu_f(zv);
    }
}

// ---------------- launcher --------------------------------------------------
extern "C" void kernel_launch(void* const* d_in, const int* in_sizes, int n_in,
                              void* d_out, int out_size)
{
    (void)in_sizes; (void)n_in; (void)out_size;
    const float* x      = (const float*)d_in[0];
    const float* emb_w  = (const float*)d_in[1];
    const float* emb_b  = (const float*)d_in[2];
    const float* in_w   = (const float*)d_in[3];
    const float* conv_w = (const float*)d_in[4];
    const float* conv_b = (const float*)d_in[5];
    const float* xp_w   = (const float*)d_in[6];
    const float* dt_w   = (const float*)d_in[7];
    const float* dt_b   = (const float*)d_in[8];
    const float* A_log  = (const float*)d_in[9];
    const float* Dparam = (const float*)d_in[10];
    const float* out_w  = (const float*)d_in[11];
    const float* norm_w = (const float*)d_in[12];
    float* out = (float*)d_out;

    float* scratch = nullptr;
    cudaGetSymbolAddress((void**)&scratch, g_scratch);
    float* h     = scratch + OFF_H;
    float* hn    = scratch + OFF_HN;
    float* xz    = scratch + OFF_XZ;
    float* xi    = scratch + OFF_XI;
    float* delta = scratch + OFF_DELTA;
    float* y     = scratch + OFF_Y;
    float* dbc   = scratch + OFF_DBC;

    // h = x @ emb_w^T + emb_b        (M=4096, N=512, K=64)
    sgemm128<true, false, false><<<dim3(DMODEL/128, T/128), 256>>>(
        x, INPUT_D, emb_w, emb_b, nullptr, h, DMODEL, INPUT_D);

    for (int i = 0; i < NL; i++) {
        const float* in_w_i   = in_w   + (size_t)i * 2 * ED * DMODEL;
        const float* conv_w_i = conv_w + (size_t)i * ED * DCONV;
        const float* conv_b_i = conv_b + (size_t)i * ED;
        const float* xp_w_i   = xp_w   + (size_t)i * 64 * ED;
        const float* dt_w_i   = dt_w   + (size_t)i * ED * DTRANK;
        const float* dt_b_i   = dt_b   + (size_t)i * ED;
        const float* A_log_i  = A_log  + (size_t)i * ED * DSTATE;
        const float* D_i      = Dparam + (size_t)i * ED;
        const float* out_w_i  = out_w  + (size_t)i * DMODEL * ED;
        const float* norm_w_i = norm_w + (size_t)i * DMODEL;

        // hn = rmsnorm(h)
        rmsnorm_k<<<T, 256>>>(h, norm_w_i, hn);

        // xz = hn @ in_proj_w^T      (M=4096, N=2048, K=512)
        sgemm128<false, false, false><<<dim3((2*ED)/128, T/128), 256>>>(
            hn, DMODEL, in_w_i, nullptr, nullptr, xz, 2*ED, DMODEL);

        // xi = silu(conv(xz[:, :ED]) + cb)
        conv_silu_k<<<(T*ED)/256, 256>>>(xz, conv_w_i, conv_b_i, xi);

        // dbc = xi @ x_proj_w^T      (M=4096, N=64, K=1024)
        xproj64<<<T/64, 256>>>(xi, xp_w_i, dbc);

        // delta = softplus(dbc[:, :32] @ dt_w^T + dt_b)   (M=4096, N=1024, K=32)
        sgemm128<true, true, false><<<dim3(ED/128, T/128), 256>>>(
            dbc, 64, dt_w_i, dt_b_i, nullptr, delta, ED, DTRANK);

        // selective scan -> y (fused +D*xi and *silu(z))
        scan_k<<<(BSZ*ED)/16, 256>>>(delta, xi, xz, dbc, A_log_i, D_i, y);

        // out = h + y @ out_proj_w^T  (M=4096, N=512, K=1024)
        float* dest = (i == NL - 1) ? out : h;
        sgemm128<false, false, true><<<dim3(DMODEL/128, T/128), 256>>>(
            y, ED, out_w_i, nullptr, h, dest, DMODEL, ED);
    }
}

// round 8
// speedup vs baseline: 1.0873x; 1.0873x over previous
#include <cuda_runtime.h>
#include <mma.h>
#include <math.h>
#include <stdint.h>

using namespace nvcuda;

// ---------------- problem constants ----------------
#define NL       2
#define DMODEL   512
#define ED       1024
#define DSTATE   16
#define DCONV    4
#define DTRANK   32
#define INPUT_D  64
#define BSZ      2
#define LSEQ     2048
#define T        (BSZ*LSEQ)          // 4096 tokens

// ---------------- scratch (single device global, no allocs) ----------------
#define OFF_H     0
#define OFF_HN    (OFF_H  + T*DMODEL)
#define OFF_XZ    (OFF_HN + T*DMODEL)
#define OFF_XI    (OFF_XZ + T*2*ED)
#define OFF_DELTA (OFF_XI + T*ED)
#define OFF_Y     (OFF_DELTA + T*ED)
#define OFF_DBC   (OFF_Y  + T*ED)
#define SCRATCH_FLOATS (OFF_DBC + T*64)

__device__ float g_scratch[SCRATCH_FLOATS];

// ---------------- helpers ----------------
__device__ __forceinline__ float softplus_f(float x) {
    return x > 20.f ? x : log1pf(__expf(x));
}
__device__ __forceinline__ float silu_f(float x) {
    return x / (1.f + __expf(-x));
}

// ---------------- TF32 tensor-core GEMM: C[M,N] = A[M,K] @ W[N,K]^T ---------
// Block tile BM x BN, K-chunk 32, 256 threads (8 warps).
// Warp layout: WARPS_M = BM/32 rows of warps, 8/WARPS_M cols.
// Each warp: 32 x WN region = 2 x (WN/16) wmma m16n16k8 fragments.
// Requires: M%BM==0, N%BN==0, K%32==0, lda/ldw multiples of 4.
template<int BM, int BN>
__global__ __launch_bounds__(256)
void gemm_tf32(const float* __restrict__ A, int lda,
               const float* __restrict__ W, int ldw,
               float* __restrict__ C, int N, int K)
{
    constexpr int WARPS_M = BM / 32;
    constexpr int WARPS_N = 8 / WARPS_M;
    constexpr int WN = BN / WARPS_N;
    constexpr int MI = 2;
    constexpr int NI = WN / 16;
    constexpr int LDS = 36;                 // 32 + 4 pad (144B rows, 16B aligned)

    __shared__ float As[BM][LDS];
    __shared__ float Ws[BN][LDS];

    const int tid = threadIdx.x;
    const int m0 = blockIdx.y * BM;
    const int n0 = blockIdx.x * BN;
    const int wid = tid >> 5;
    const int wm = (wid % WARPS_M) * 32;
    const int wn = (wid / WARPS_M) * WN;

    wmma::fragment<wmma::accumulator, 16, 16, 8, float> acc[MI][NI];
#pragma unroll
    for (int mi = 0; mi < MI; mi++)
#pragma unroll
        for (int ni = 0; ni < NI; ni++)
            wmma::fill_fragment(acc[mi][ni], 0.0f);

    constexpr int A_F4 = BM * 8;            // float4 count for A tile (BM x 32)
    constexpr int TOT_F4 = A_F4 + BN * 8;
    constexpr int ITER = TOT_F4 / 256;

    for (int k0 = 0; k0 < K; k0 += 32) {
        __syncthreads();
#pragma unroll
        for (int i = 0; i < ITER; i++) {
            int lin = tid + i * 256;
            if (lin < A_F4) {
                int row = lin >> 3, c = (lin & 7) * 4;
                float4 v = *reinterpret_cast<const float4*>(
                    &A[(size_t)(m0 + row) * lda + k0 + c]);
                *reinterpret_cast<float4*>(&As[row][c]) = v;
            } else {
                int l2 = lin - A_F4;
                int row = l2 >> 3, c = (l2 & 7) * 4;
                float4 v = *reinterpret_cast<const float4*>(
                    &W[(size_t)(n0 + row) * ldw + k0 + c]);
                *reinterpret_cast<float4*>(&Ws[row][c]) = v;
            }
        }
        __syncthreads();

#pragma unroll
        for (int ks = 0; ks < 4; ks++) {
            const int kk = ks * 8;
            wmma::fragment<wmma::matrix_a, 16, 16, 8,
                           wmma::precision::tf32, wmma::row_major> a_frag[MI];
            wmma::fragment<wmma::matrix_b, 16, 16, 8,
                           wmma::precision::tf32, wmma::col_major> b_frag[NI];
#pragma unroll
            for (int mi = 0; mi < MI; mi++) {
                wmma::load_matrix_sync(a_frag[mi], &As[wm + mi * 16][kk], LDS);
#pragma unroll
                for (int t = 0; t < a_frag[mi].num_elements; t++)
                    a_frag[mi].x[t] = wmma::__float_to_tf32(a_frag[mi].x[t]);
            }
#pragma unroll
            for (int ni = 0; ni < NI; ni++) {
                wmma::load_matrix_sync(b_frag[ni], &Ws[wn + ni * 16][kk], LDS);
#pragma unroll
                for (int t = 0; t < b_frag[ni].num_elements; t++)
                    b_frag[ni].x[t] = wmma::__float_to_tf32(b_frag[ni].x[t]);
            }
#pragma unroll
            for (int mi = 0; mi < MI; mi++)
#pragma unroll
                for (int ni = 0; ni < NI; ni++)
                    wmma::mma_sync(acc[mi][ni], a_frag[mi], b_frag[ni], acc[mi][ni]);
        }
    }

#pragma unroll
    for (int mi = 0; mi < MI; mi++)
#pragma unroll
        for (int ni = 0; ni < NI; ni++)
            wmma::store_matrix_sync(
                &C[(size_t)(m0 + wm + mi * 16) * N + n0 + wn + ni * 16],
                acc[mi][ni], N, wmma::mem_row_major);
}

// ---------------- elementwise epilogues -------------------------------------
__global__ __launch_bounds__(256)
void bias_add_k(float* __restrict__ v, const float* __restrict__ b, int ncols)
{
    const int idx = blockIdx.x * 256 + threadIdx.x;
    v[idx] += b[idx % ncols];
}

__global__ __launch_bounds__(256)
void softplus_bias_k(float* __restrict__ v, const float* __restrict__ b)
{
    const int idx = blockIdx.x * 256 + threadIdx.x;
    v[idx] = softplus_f(v[idx] + b[idx & (ED - 1)]);
}

__global__ __launch_bounds__(256)
void add_k(float* __restrict__ dest, const float* __restrict__ a,
           const float* __restrict__ b)
{
    const int idx = blockIdx.x * 256 + threadIdx.x;
    dest[idx] = a[idx] + b[idx];
}

// ---------------- rmsnorm over DMODEL=512, one block per token --------------
__global__ __launch_bounds__(256)
void rmsnorm_k(const float* __restrict__ h, const float* __restrict__ w,
               float* __restrict__ out)
{
    const int t = blockIdx.x;
    const float* row = h + (size_t)t * DMODEL;
    const int tid = threadIdx.x;
    float v0 = row[tid], v1 = row[tid + 256];
    float ss = v0 * v0 + v1 * v1;
#pragma unroll
    for (int o = 16; o; o >>= 1) ss += __shfl_xor_sync(0xffffffffu, ss, o);
    __shared__ float red[8];
    if ((tid & 31) == 0) red[tid >> 5] = ss;
    __syncthreads();
    float tot = red[0] + red[1] + red[2] + red[3] +
                red[4] + red[5] + red[6] + red[7];
    float scale = rsqrtf(tot * (1.f / DMODEL) + 1e-5f);
    out[(size_t)t * DMODEL + tid]       = v0 * scale * w[tid];
    out[(size_t)t * DMODEL + tid + 256] = v1 * scale * w[tid + 256];
}

// ---------------- depthwise causal conv (k=4) + bias + silu -----------------
__global__ __launch_bounds__(256)
void conv_silu_k(const float* __restrict__ xz, const float* __restrict__ cw,
                 const float* __restrict__ cb, float* __restrict__ xi)
{
    const int idx = blockIdx.x * 256 + threadIdx.x;   // t*ED + e
    const int e = idx & (ED - 1);
    const int t = idx >> 10;
    const int l = t & (LSEQ - 1);
    const float* base = xz + (size_t)t * (2 * ED) + e;
    float acc = cb[e];
#pragma unroll
    for (int k = 0; k < DCONV; k++) {
        int ll = l - (DCONV - 1) + k;
        if (ll >= 0)
            acc = fmaf(base[(ptrdiff_t)(k - (DCONV - 1)) * (2 * ED)],
                       cw[e * DCONV + k], acc);
    }
    xi[idx] = silu_f(acc);
}

// ---------------- selective scan ---------------------------------------------
// 2 channels per warp, 16 lanes per channel (one state n each).
__global__ __launch_bounds__(256)
void scan_k(const float* __restrict__ delta, const float* __restrict__ xi,
            const float* __restrict__ xz, const float* __restrict__ dbc,
            const float* __restrict__ A_log, const float* __restrict__ Dp,
            float* __restrict__ y)
{
    const int gid = blockIdx.x * 256 + threadIdx.x;
    const int c = gid >> 4;           // channel 0..2047 (b*ED + e)
    const int n = gid & 15;
    const int b = c >> 10;
    const int e = c & (ED - 1);

    const float a  = -__expf(A_log[e * DSTATE + n]);
    const float dE = Dp[e];

    float s = 0.f;
    const size_t tb = (size_t)b * LSEQ;
    for (int l = 0; l < LSEQ; l++) {
        const size_t t = tb + l;
        float dv = delta[t * ED + e];
        float xv = xi[t * ED + e];
        float zv = xz[t * (2 * ED) + ED + e];
        float Bv = dbc[t * 64 + DTRANK + n];
        float Cv = dbc[t * 64 + DTRANK + DSTATE + n];
        float dA = __expf(dv * a);
        s = fmaf(dA, s, dv * xv * Bv);
        float p = s * Cv;
        p += __shfl_xor_sync(0xffffffffu, p, 8, 16);
        p += __shfl_xor_sync(0xffffffffu, p, 4, 16);
        p += __shfl_xor_sync(0xffffffffu, p, 2, 16);
        p += __shfl_xor_sync(0xffffffffu, p, 1, 16);
        if (n == 0)
            y[t * ED + e] = (p + dE * xv) * silu_f(zv);
    }
}

// ---------------- launcher ----------------------------------------------------
extern "C" void kernel_launch(void* const* d_in, const int* in_sizes, int n_in,
                              void* d_out, int out_size)
{
    (void)in_sizes; (void)n_in; (void)out_size;
    const float* x      = (const float*)d_in[0];
    const float* emb_w  = (const float*)d_in[1];
    const float* emb_b  = (const float*)d_in[2];
    const float* in_w   = (const float*)d_in[3];
    const float* conv_w = (const float*)d_in[4];
    const float* conv_b = (const float*)d_in[5];
    const float* xp_w   = (const float*)d_in[6];
    const float* dt_w   = (const float*)d_in[7];
    const float* dt_b   = (const float*)d_in[8];
    const float* A_log  = (const float*)d_in[9];
    const float* Dparam = (const float*)d_in[10];
    const float* out_w  = (const float*)d_in[11];
    const float* norm_w = (const float*)d_in[12];
    float* out = (float*)d_out;

    float* scratch = nullptr;
    cudaGetSymbolAddress((void**)&scratch, g_scratch);
    float* h     = scratch + OFF_H;
    float* hn    = scratch + OFF_HN;   // rmsnorm out; reused as out_proj tmp
    float* xz    = scratch + OFF_XZ;
    float* xi    = scratch + OFF_XI;
    float* delta = scratch + OFF_DELTA;
    float* y     = scratch + OFF_Y;
    float* dbc   = scratch + OFF_DBC;

    // h = x @ emb_w^T ; h += emb_b          (M=4096, N=512, K=64)
    gemm_tf32<128,128><<<dim3(DMODEL/128, T/128), 256>>>(
        x, INPUT_D, emb_w, INPUT_D, h, DMODEL, INPUT_D);
    bias_add_k<<<(T*DMODEL)/256, 256>>>(h, emb_b, DMODEL);

    for (int i = 0; i < NL; i++) {
        const float* in_w_i   = in_w   + (size_t)i * 2 * ED * DMODEL;
        const float* conv_w_i = conv_w + (size_t)i * ED * DCONV;
        const float* conv_b_i = conv_b + (size_t)i * ED;
        const float* xp_w_i   = xp_w   + (size_t)i * 64 * ED;
        const float* dt_w_i   = dt_w   + (size_t)i * ED * DTRANK;
        const float* dt_b_i   = dt_b   + (size_t)i * ED;
        const float* A_log_i  = A_log  + (size_t)i * ED * DSTATE;
        const float* D_i      = Dparam + (size_t)i * ED;
        const float* out_w_i  = out_w  + (size_t)i * DMODEL * ED;
        const float* norm_w_i = norm_w + (size_t)i * DMODEL;

        // hn = rmsnorm(h)
        rmsnorm_k<<<T, 256>>>(h, norm_w_i, hn);

        // xz = hn @ in_proj_w^T              (M=4096, N=2048, K=512)
        gemm_tf32<128,128><<<dim3((2*ED)/128, T/128), 256>>>(
            hn, DMODEL, in_w_i, DMODEL, xz, 2*ED, DMODEL);

        // xi = silu(conv(xz[:, :ED]) + cb)
        conv_silu_k<<<(T*ED)/256, 256>>>(xz, conv_w_i, conv_b_i, xi);

        // dbc = xi @ x_proj_w^T              (M=4096, N=64, K=1024)
        gemm_tf32<64,64><<<dim3(1, T/64), 256>>>(
            xi, ED, xp_w_i, ED, dbc, 64, ED);

        // delta = softplus(dbc[:, :32] @ dt_w^T + dt_b)   (M=4096, N=1024, K=32)
        gemm_tf32<128,128><<<dim3(ED/128, T/128), 256>>>(
            dbc, 64, dt_w_i, DTRANK, delta, ED, DTRANK);
        softplus_bias_k<<<(T*ED)/256, 256>>>(delta, dt_b_i);

        // selective scan -> y (fused +D*xi and *silu(z))
        scan_k<<<(BSZ*ED)/16, 256>>>(delta, xi, xz, dbc, A_log_i, D_i, y);

        // tmp(hn) = y @ out_proj_w^T ; dest = h + tmp      (M=4096, N=512, K=1024)
        gemm_tf32<128,128><<<dim3(DMODEL/128, T/128), 256>>>(
            y, ED, out_w_i, ED, hn, DMODEL, ED);
        float* dest = (i == NL - 1) ? out : h;
        add_k<<<(T*DMODEL)/256, 256>>>(dest, h, hn);
    }
}

// round 11
// speedup vs baseline: 3.3674x; 3.0971x over previous
#include <cuda_runtime.h>
#include <mma.h>
#include <math.h>
#include <stdint.h>

using namespace nvcuda;

// ---------------- problem constants ----------------
#define NL       2
#define DMODEL   512
#define ED       1024
#define DSTATE   16
#define DCONV    4
#define DTRANK   32
#define INPUT_D  64
#define BSZ      2
#define LSEQ     2048
#define T        (BSZ*LSEQ)          // 4096 tokens

// chunked scan
#define NC       16                  // chunks per sequence
#define CL       (LSEQ/NC)           // 128 steps per chunk
#define NCHAN    (BSZ*ED)            // 2048 scalar channels

// ---------------- scratch (single device global, no allocs) ----------------
#define OFF_H     0
#define OFF_HN    (OFF_H  + T*DMODEL)
#define OFF_XZ    (OFF_HN + T*DMODEL)
#define OFF_XI    (OFF_XZ + T*2*ED)
#define OFF_DELTA (OFF_XI + T*ED)
#define OFF_Y     (OFF_DELTA + T*ED)
#define OFF_DBC   (OFF_Y  + T*ED)
#define OFF_P     (OFF_DBC + T*64)
#define OFF_Q     (OFF_P + NCHAN*NC*DSTATE)
#define OFF_S0    (OFF_Q + NCHAN*NC*DSTATE)
#define SCRATCH_FLOATS (OFF_S0 + NCHAN*NC*DSTATE)

__device__ float g_scratch[SCRATCH_FLOATS];

// ---------------- helpers ----------------
__device__ __forceinline__ float softplus_f(float x) {
    return x > 20.f ? x : log1pf(__expf(x));
}
__device__ __forceinline__ float silu_f(float x) {
    return x / (1.f + __expf(-x));
}

// ---------------- TF32 tensor-core GEMM: C[M,N] = A[M,K] @ W[N,K]^T ---------
template<int BM, int BN>
__global__ __launch_bounds__(256)
void gemm_tf32(const float* __restrict__ A, int lda,
               const float* __restrict__ W, int ldw,
               float* __restrict__ C, int N, int K)
{
    constexpr int WARPS_M = BM / 32;
    constexpr int WARPS_N = 8 / WARPS_M;
    constexpr int WN = BN / WARPS_N;
    constexpr int MI = 2;
    constexpr int NI = WN / 16;
    constexpr int LDS = 36;

    __shared__ float As[BM][LDS];
    __shared__ float Ws[BN][LDS];

    const int tid = threadIdx.x;
    const int m0 = blockIdx.y * BM;
    const int n0 = blockIdx.x * BN;
    const int wid = tid >> 5;
    const int wm = (wid % WARPS_M) * 32;
    const int wn = (wid / WARPS_M) * WN;

    wmma::fragment<wmma::accumulator, 16, 16, 8, float> acc[MI][NI];
#pragma unroll
    for (int mi = 0; mi < MI; mi++)
#pragma unroll
        for (int ni = 0; ni < NI; ni++)
            wmma::fill_fragment(acc[mi][ni], 0.0f);

    constexpr int A_F4 = BM * 8;
    constexpr int TOT_F4 = A_F4 + BN * 8;
    constexpr int ITER = TOT_F4 / 256;

    for (int k0 = 0; k0 < K; k0 += 32) {
        __syncthreads();
#pragma unroll
        for (int i = 0; i < ITER; i++) {
            int lin = tid + i * 256;
            if (lin < A_F4) {
                int row = lin >> 3, c = (lin & 7) * 4;
                float4 v = *reinterpret_cast<const float4*>(
                    &A[(size_t)(m0 + row) * lda + k0 + c]);
                *reinterpret_cast<float4*>(&As[row][c]) = v;
            } else {
                int l2 = lin - A_F4;
                int row = l2 >> 3, c = (l2 & 7) * 4;
                float4 v = *reinterpret_cast<const float4*>(
                    &W[(size_t)(n0 + row) * ldw + k0 + c]);
                *reinterpret_cast<float4*>(&Ws[row][c]) = v;
            }
        }
        __syncthreads();

#pragma unroll
        for (int ks = 0; ks < 4; ks++) {
            const int kk = ks * 8;
            wmma::fragment<wmma::matrix_a, 16, 16, 8,
                           wmma::precision::tf32, wmma::row_major> a_frag[MI];
            wmma::fragment<wmma::matrix_b, 16, 16, 8,
                           wmma::precision::tf32, wmma::col_major> b_frag[NI];
#pragma unroll
            for (int mi = 0; mi < MI; mi++) {
                wmma::load_matrix_sync(a_frag[mi], &As[wm + mi * 16][kk], LDS);
#pragma unroll
                for (int t = 0; t < a_frag[mi].num_elements; t++)
                    a_frag[mi].x[t] = wmma::__float_to_tf32(a_frag[mi].x[t]);
            }
#pragma unroll
            for (int ni = 0; ni < NI; ni++) {
                wmma::load_matrix_sync(b_frag[ni], &Ws[wn + ni * 16][kk], LDS);
#pragma unroll
                for (int t = 0; t < b_frag[ni].num_elements; t++)
                    b_frag[ni].x[t] = wmma::__float_to_tf32(b_frag[ni].x[t]);
            }
#pragma unroll
            for (int mi = 0; mi < MI; mi++)
#pragma unroll
                for (int ni = 0; ni < NI; ni++)
                    wmma::mma_sync(acc[mi][ni], a_frag[mi], b_frag[ni], acc[mi][ni]);
        }
    }

#pragma unroll
    for (int mi = 0; mi < MI; mi++)
#pragma unroll
        for (int ni = 0; ni < NI; ni++)
            wmma::store_matrix_sync(
                &C[(size_t)(m0 + wm + mi * 16) * N + n0 + wn + ni * 16],
                acc[mi][ni], N, wmma::mem_row_major);
}

// ---------------- elementwise epilogues -------------------------------------
__global__ __launch_bounds__(256)
void bias_add_k(float* __restrict__ v, const float* __restrict__ b, int ncols)
{
    const int idx = blockIdx.x * 256 + threadIdx.x;
    v[idx] += b[idx % ncols];
}

__global__ __launch_bounds__(256)
void softplus_bias_k(float* __restrict__ v, const float* __restrict__ b)
{
    const int idx = blockIdx.x * 256 + threadIdx.x;
    v[idx] = softplus_f(v[idx] + b[idx & (ED - 1)]);
}

__global__ __launch_bounds__(256)
void add_k(float* __restrict__ dest, const float* __restrict__ a,
           const float* __restrict__ b)
{
    const int idx = blockIdx.x * 256 + threadIdx.x;
    dest[idx] = a[idx] + b[idx];
}

// ---------------- rmsnorm over DMODEL=512, one block per token --------------
__global__ __launch_bounds__(256)
void rmsnorm_k(const float* __restrict__ h, const float* __restrict__ w,
               float* __restrict__ out)
{
    const int t = blockIdx.x;
    const float* row = h + (size_t)t * DMODEL;
    const int tid = threadIdx.x;
    float v0 = row[tid], v1 = row[tid + 256];
    float ss = v0 * v0 + v1 * v1;
#pragma unroll
    for (int o = 16; o; o >>= 1) ss += __shfl_xor_sync(0xffffffffu, ss, o);
    __shared__ float red[8];
    if ((tid & 31) == 0) red[tid >> 5] = ss;
    __syncthreads();
    float tot = red[0] + red[1] + red[2] + red[3] +
                red[4] + red[5] + red[6] + red[7];
    float scale = rsqrtf(tot * (1.f / DMODEL) + 1e-5f);
    out[(size_t)t * DMODEL + tid]       = v0 * scale * w[tid];
    out[(size_t)t * DMODEL + tid + 256] = v1 * scale * w[tid + 256];
}

// ---------------- depthwise causal conv (k=4) + bias + silu -----------------
__global__ __launch_bounds__(256)
void conv_silu_k(const float* __restrict__ xz, const float* __restrict__ cw,
                 const float* __restrict__ cb, float* __restrict__ xi)
{
    const int idx = blockIdx.x * 256 + threadIdx.x;   // t*ED + e
    const int e = idx & (ED - 1);
    const int t = idx >> 10;
    const int l = t & (LSEQ - 1);
    const float* base = xz + (size_t)t * (2 * ED) + e;
    float acc = cb[e];
#pragma unroll
    for (int k = 0; k < DCONV; k++) {
        int ll = l - (DCONV - 1) + k;
        if (ll >= 0)
            acc = fmaf(base[(ptrdiff_t)(k - (DCONV - 1)) * (2 * ED)],
                       cw[e * DCONV + k], acc);
    }
    xi[idx] = silu_f(acc);
}

// ---------------- chunked selective scan -------------------------------------
// scalar recurrence per (b,e,n):  s_t = exp(delta_t * a_n) * s_{t-1} + delta_t*xi_t*B_t(n)
// pass 1: per chunk, compute P = prod(dA), Q = chunk-local scan end (s_init = 0)
__global__ __launch_bounds__(256)
void scan_p1(const float* __restrict__ delta, const float* __restrict__ xi,
             const float* __restrict__ dbc, const float* __restrict__ A_log,
             float* __restrict__ Pa, float* __restrict__ Qa)
{
    const int tid = threadIdx.x;
    const int j   = blockIdx.x >> 7;           // chunk 0..15
    const int cb  = blockIdx.x & 127;          // channel block
    const int cl  = tid >> 4;
    const int n   = tid & 15;
    const int c   = cb * 16 + cl;              // 0..2047
    const int b   = c >> 10;
    const int e   = c & (ED - 1);

    const float a = -__expf(A_log[e * DSTATE + n]);
    const size_t t0 = (size_t)b * LSEQ + (size_t)j * CL;
    const float* dp = delta + t0 * ED + e;
    const float* xp = xi    + t0 * ED + e;
    const float* bp = dbc   + t0 * 64 + DTRANK + n;

    float P = 1.f, q = 0.f;
#pragma unroll 4
    for (int l = 0; l < CL; l++) {
        float dv = dp[(size_t)l * ED];
        float xv = xp[(size_t)l * ED];
        float Bv = bp[(size_t)l * 64];
        float dA = __expf(dv * a);
        P *= dA;
        q = fmaf(dA, q, dv * xv * Bv);
    }
    const int o = (c * NC + j) * DSTATE + n;
    Pa[o] = P;
    Qa[o] = q;
}

// pass 2: serial scan over the 16 chunks per (c,n) -> chunk-start states
__global__ __launch_bounds__(256)
void scan_p2(const float* __restrict__ Pa, const float* __restrict__ Qa,
             float* __restrict__ S0)
{
    const int gid = blockIdx.x * 256 + threadIdx.x;   // 32768 threads
    const int c = gid >> 4;
    const int n = gid & 15;
    const int base = c * NC * DSTATE + n;
    float s = 0.f;
#pragma unroll
    for (int jj = 0; jj < NC; jj++) {
        S0[base + jj * DSTATE] = s;
        s = fmaf(Pa[base + jj * DSTATE], s, Qa[base + jj * DSTATE]);
    }
}

// pass 3: re-run each chunk seeded with its start state; produce y
__global__ __launch_bounds__(256)
void scan_p3(const float* __restrict__ delta, const float* __restrict__ xi,
             const float* __restrict__ xz, const float* __restrict__ dbc,
             const float* __restrict__ A_log, const float* __restrict__ Dp,
             const float* __restrict__ S0, float* __restrict__ y)
{
    const int tid = threadIdx.x;
    const int j   = blockIdx.x >> 7;
    const int cb  = blockIdx.x & 127;
    const int cl  = tid >> 4;
    const int n   = tid & 15;
    const int c   = cb * 16 + cl;
    const int b   = c >> 10;
    const int e   = c & (ED - 1);

    const float a  = -__expf(A_log[e * DSTATE + n]);
    const float dE = Dp[e];
    const size_t t0 = (size_t)b * LSEQ + (size_t)j * CL;
    const float* dp = delta + t0 * ED + e;
    const float* xp = xi    + t0 * ED + e;
    const float* zp = xz    + t0 * (2 * ED) + ED + e;
    const float* bp = dbc   + t0 * 64 + DTRANK + n;
    const float* cp = dbc   + t0 * 64 + DTRANK + DSTATE + n;
    float*       yp = y     + t0 * ED + e;

    float s = S0[(c * NC + j) * DSTATE + n];
#pragma unroll 4
    for (int l = 0; l < CL; l++) {
        float dv = dp[(size_t)l * ED];
        float xv = xp[(size_t)l * ED];
        float Bv = bp[(size_t)l * 64];
        float Cv = cp[(size_t)l * 64];
        float dA = __expf(dv * a);
        s = fmaf(dA, s, dv * xv * Bv);
        float p = s * Cv;
        p += __shfl_xor_sync(0xffffffffu, p, 8, 16);
        p += __shfl_xor_sync(0xffffffffu, p, 4, 16);
        p += __shfl_xor_sync(0xffffffffu, p, 2, 16);
        p += __shfl_xor_sync(0xffffffffu, p, 1, 16);
        if (n == 0) {
            float zv = zp[(size_t)l * (2 * ED)];
            yp[(size_t)l * ED] = (p + dE * xv) * silu_f(zv);
        }
    }
}

// ---------------- launcher ----------------------------------------------------
extern "C" void kernel_launch(void* const* d_in, const int* in_sizes, int n_in,
                              void* d_out, int out_size)
{
    (void)in_sizes; (void)n_in; (void)out_size;
    const float* x      = (const float*)d_in[0];
    const float* emb_w  = (const float*)d_in[1];
    const float* emb_b  = (const float*)d_in[2];
    const float* in_w   = (const float*)d_in[3];
    const float* conv_w = (const float*)d_in[4];
    const float* conv_b = (const float*)d_in[5];
    const float* xp_w   = (const float*)d_in[6];
    const float* dt_w   = (const float*)d_in[7];
    const float* dt_b   = (const float*)d_in[8];
    const float* A_log  = (const float*)d_in[9];
    const float* Dparam = (const float*)d_in[10];
    const float* out_w  = (const float*)d_in[11];
    const float* norm_w = (const float*)d_in[12];
    float* out = (float*)d_out;

    float* scratch = nullptr;
    cudaGetSymbolAddress((void**)&scratch, g_scratch);
    float* h     = scratch + OFF_H;
    float* hn    = scratch + OFF_HN;   // rmsnorm out; reused as out_proj tmp
    float* xz    = scratch + OFF_XZ;
    float* xi    = scratch + OFF_XI;
    float* delta = scratch + OFF_DELTA;
    float* y     = scratch + OFF_Y;
    float* dbc   = scratch + OFF_DBC;
    float* Pa    = scratch + OFF_P;
    float* Qa    = scratch + OFF_Q;
    float* S0    = scratch + OFF_S0;

    // h = x @ emb_w^T ; h += emb_b          (M=4096, N=512, K=64)
    gemm_tf32<128,128><<<dim3(DMODEL/128, T/128), 256>>>(
        x, INPUT_D, emb_w, INPUT_D, h, DMODEL, INPUT_D);
    bias_add_k<<<(T*DMODEL)/256, 256>>>(h, emb_b, DMODEL);

    for (int i = 0; i < NL; i++) {
        const float* in_w_i   = in_w   + (size_t)i * 2 * ED * DMODEL;
        const float* conv_w_i = conv_w + (size_t)i * ED * DCONV;
        const float* conv_b_i = conv_b + (size_t)i * ED;
        const float* xp_w_i   = xp_w   + (size_t)i * 64 * ED;
        const float* dt_w_i   = dt_w   + (size_t)i * ED * DTRANK;
        const float* dt_b_i   = dt_b   + (size_t)i * ED;
        const float* A_log_i  = A_log  + (size_t)i * ED * DSTATE;
        const float* D_i      = Dparam + (size_t)i * ED;
        const float* out_w_i  = out_w  + (size_t)i * DMODEL * ED;
        const float* norm_w_i = norm_w + (size_t)i * DMODEL;

        // hn = rmsnorm(h)
        rmsnorm_k<<<T, 256>>>(h, norm_w_i, hn);

        // xz = hn @ in_proj_w^T              (M=4096, N=2048, K=512)
        gemm_tf32<128,128><<<dim3((2*ED)/128, T/128), 256>>>(
            hn, DMODEL, in_w_i, DMODEL, xz, 2*ED, DMODEL);

        // xi = silu(conv(xz[:, :ED]) + cb)
        conv_silu_k<<<(T*ED)/256, 256>>>(xz, conv_w_i, conv_b_i, xi);

        // dbc = xi @ x_proj_w^T              (M=4096, N=64, K=1024)
        gemm_tf32<64,64><<<dim3(1, T/64), 256>>>(
            xi, ED, xp_w_i, ED, dbc, 64, ED);

        // delta = softplus(dbc[:, :32] @ dt_w^T + dt_b)   (M=4096, N=1024, K=32)
        gemm_tf32<128,128><<<dim3(ED/128, T/128), 256>>>(
            dbc, 64, dt_w_i, DTRANK, delta, ED, DTRANK);
        softplus_bias_k<<<(T*ED)/256, 256>>>(delta, dt_b_i);

        // chunked selective scan -> y
        scan_p1<<<NC*128, 256>>>(delta, xi, dbc, A_log_i, Pa, Qa);
        scan_p2<<<(NCHAN*DSTATE)/256, 256>>>(Pa, Qa, S0);
        scan_p3<<<NC*128, 256>>>(delta, xi, xz, dbc, A_log_i, D_i, S0, y);

        // tmp(hn) = y @ out_proj_w^T ; dest = h + tmp      (M=4096, N=512, K=1024)
        gemm_tf32<128,128><<<dim3(DMODEL/128, T/128), 256>>>(
            y, ED, out_w_i, ED, hn, DMODEL, ED);
        float* dest = (i == NL - 1) ? out : h;
        add_k<<<(T*DMODEL)/256, 256>>>(dest, h, hn);
    }
}

// round 12
// speedup vs baseline: 3.6993x; 1.0986x over previous
#include <cuda_runtime.h>
#include <cuda_pipeline.h>
#include <mma.h>
#include <math.h>
#include <stdint.h>

using namespace nvcuda;

// ---------------- problem constants ----------------
#define NL       2
#define DMODEL   512
#define ED       1024
#define DSTATE   16
#define DCONV    4
#define DTRANK   32
#define INPUT_D  64
#define BSZ      2
#define LSEQ     2048
#define T        (BSZ*LSEQ)          // 4096 tokens

// chunked scan
#define NC       16
#define CL       (LSEQ/NC)           // 128
#define NCHAN    (BSZ*ED)            // 2048

// ---------------- scratch (single device global, no allocs) ----------------
#define OFF_H     0
#define OFF_HN    (OFF_H  + T*DMODEL)
#define OFF_XZ    (OFF_HN + T*DMODEL)
#define OFF_XI    (OFF_XZ + T*2*ED)
#define OFF_DELTA (OFF_XI + T*ED)
#define OFF_Y     (OFF_DELTA + T*ED)
#define OFF_DBC   (OFF_Y  + T*ED)
#define OFF_P     (OFF_DBC + T*64)
#define OFF_Q     (OFF_P + NCHAN*NC*DSTATE)
#define OFF_S0    (OFF_Q + NCHAN*NC*DSTATE)
#define OFF_DBCP  (OFF_S0 + NCHAN*NC*DSTATE)
#define SCRATCH_FLOATS (OFF_DBCP + 4*T*64)

__device__ float g_scratch[SCRATCH_FLOATS];

// ---------------- helpers ----------------
__device__ __forceinline__ float softplus_f(float x) {
    return x > 20.f ? x : log1pf(__expf(x));
}
__device__ __forceinline__ float silu_f(float x) {
    return x / (1.f + __expf(-x));
}

// ---------------- TF32 tensor-core GEMM: C[M,N] = A[M,K] @ W[N,K]^T ---------
// Double-buffered cp.async pipeline, dynamic smem, fused epilogues.
// Split-K via gridDim.z: each z handles its own K columns (A/W offset z*K),
// writing to C + z*c_zstride.
template<int BM, int BN, int BK, bool BIAS, bool SOFTPLUS, bool RES>
__global__ __launch_bounds__(256)
void gemm_tf32(const float* __restrict__ A, int lda,
               const float* __restrict__ W, int ldw,
               const float* __restrict__ bias,
               const float* __restrict__ res,
               float* __restrict__ C, int N, int K, size_t c_zstride)
{
    constexpr int WARPS_M = BM / 32;
    constexpr int WARPS_N = 8 / WARPS_M;
    constexpr int WN = BN / WARPS_N;
    constexpr int MI = 2;
    constexpr int NI = WN / 16;
    constexpr int LDS = BK + 4;

    extern __shared__ float sm[];
    float* As = sm;                      // [2][BM][LDS]
    float* Ws = sm + 2 * BM * LDS;       // [2][BN][LDS]

    const int tid = threadIdx.x;
    const int m0 = blockIdx.y * BM;
    const int n0 = blockIdx.x * BN;
    const int z  = blockIdx.z;
    A += (size_t)z * K;
    W += (size_t)z * K;
    C += (size_t)z * c_zstride;

    const int wid = tid >> 5;
    const int wm = (wid % WARPS_M) * 32;
    const int wn = (wid / WARPS_M) * WN;

    wmma::fragment<wmma::accumulator, 16, 16, 8, float> acc[MI][NI];
#pragma unroll
    for (int mi = 0; mi < MI; mi++)
#pragma unroll
        for (int ni = 0; ni < NI; ni++)
            wmma::fill_fragment(acc[mi][ni], 0.0f);

    constexpr int F4R   = BK / 4;            // float4 per row
    constexpr int A_F4  = BM * F4R;
    constexpr int TOT   = A_F4 + BN * F4R;
    constexpr int ITER  = TOT / 256;

    auto load_stage = [&](int s, int k0) {
#pragma unroll
        for (int i = 0; i < ITER; i++) {
            int lin = tid + i * 256;
            if (lin < A_F4) {
                int row = lin / F4R, c = (lin % F4R) * 4;
                __pipeline_memcpy_async(
                    &As[(size_t)(s * BM + row) * LDS + c],
                    &A[(size_t)(m0 + row) * lda + k0 + c], 16);
            } else {
                int l2 = lin - A_F4;
                int row = l2 / F4R, c = (l2 % F4R) * 4;
                __pipeline_memcpy_async(
                    &Ws[(size_t)(s * BN + row) * LDS + c],
                    &W[(size_t)(n0 + row) * ldw + k0 + c], 16);
            }
        }
        __pipeline_commit();
    };

    const int nk = K / BK;
    load_stage(0, 0);

    for (int kb = 0; kb < nk; kb++) {
        if (kb + 1 < nk) {
            load_stage((kb + 1) & 1, (kb + 1) * BK);
            __pipeline_wait_prior(1);
        } else {
            __pipeline_wait_prior(0);
        }
        __syncthreads();

        const int st = kb & 1;
#pragma unroll
        for (int ks = 0; ks < BK / 8; ks++) {
            const int kk = ks * 8;
            wmma::fragment<wmma::matrix_a, 16, 16, 8,
                           wmma::precision::tf32, wmma::row_major> a_frag[MI];
            wmma::fragment<wmma::matrix_b, 16, 16, 8,
                           wmma::precision::tf32, wmma::col_major> b_frag[NI];
#pragma unroll
            for (int mi = 0; mi < MI; mi++) {
                wmma::load_matrix_sync(a_frag[mi],
                    &As[(size_t)(st * BM + wm + mi * 16) * LDS + kk], LDS);
#pragma unroll
                for (int t = 0; t < a_frag[mi].num_elements; t++)
                    a_frag[mi].x[t] = wmma::__float_to_tf32(a_frag[mi].x[t]);
            }
#pragma unroll
            for (int ni = 0; ni < NI; ni++) {
                wmma::load_matrix_sync(b_frag[ni],
                    &Ws[(size_t)(st * BN + wn + ni * 16) * LDS + kk], LDS);
#pragma unroll
                for (int t = 0; t < b_frag[ni].num_elements; t++)
                    b_frag[ni].x[t] = wmma::__float_to_tf32(b_frag[ni].x[t]);
            }
#pragma unroll
            for (int mi = 0; mi < MI; mi++)
#pragma unroll
                for (int ni = 0; ni < NI; ni++)
                    wmma::mma_sync(acc[mi][ni], a_frag[mi], b_frag[ni], acc[mi][ni]);
        }
        __syncthreads();
    }

    if constexpr (BIAS || SOFTPLUS || RES) {
        // stage through smem for element-indexed epilogue
        float* stg = sm + (size_t)wid * (32 * WN);
#pragma unroll
        for (int mi = 0; mi < MI; mi++)
#pragma unroll
            for (int ni = 0; ni < NI; ni++)
                wmma::store_matrix_sync(&stg[(mi * 16) * WN + ni * 16],
                                        acc[mi][ni], WN, wmma::mem_row_major);
        __syncwarp();
        const int lane = tid & 31;
        const size_t m = m0 + wm + lane;
#pragma unroll
        for (int c = 0; c < WN; c += 4) {
            float4 v = *reinterpret_cast<float4*>(&stg[lane * WN + c]);
            const int n = n0 + wn + c;
            if (BIAS) {
                v.x += bias[n];     v.y += bias[n + 1];
                v.z += bias[n + 2]; v.w += bias[n + 3];
            }
            if (SOFTPLUS) {
                v.x = softplus_f(v.x); v.y = softplus_f(v.y);
                v.z = softplus_f(v.z); v.w = softplus_f(v.w);
            }
            if (RES) {
                float4 r = *reinterpret_cast<const float4*>(&res[m * N + n]);
                v.x += r.x; v.y += r.y; v.z += r.z; v.w += r.w;
            }
            *reinterpret_cast<float4*>(&C[m * N + n]) = v;
        }
    } else {
#pragma unroll
        for (int mi = 0; mi < MI; mi++)
#pragma unroll
            for (int ni = 0; ni < NI; ni++)
                wmma::store_matrix_sync(
                    &C[(size_t)(m0 + wm + mi * 16) * N + n0 + wn + ni * 16],
                    acc[mi][ni], N, wmma::mem_row_major);
    }
}

// ---------------- split-K reduction for x_proj -------------------------------
__global__ __launch_bounds__(256)
void reduce4_k(const float* __restrict__ p, float* __restrict__ dbc)
{
    const int i = blockIdx.x * 256 + threadIdx.x;
    dbc[i] = (p[i] + p[i + T*64]) + (p[i + 2*T*64] + p[i + 3*T*64]);
}

// ---------------- rmsnorm over DMODEL=512, one block per token --------------
__global__ __launch_bounds__(256)
void rmsnorm_k(const float* __restrict__ h, const float* __restrict__ w,
               float* __restrict__ out)
{
    const int t = blockIdx.x;
    const float* row = h + (size_t)t * DMODEL;
    const int tid = threadIdx.x;
    float v0 = row[tid], v1 = row[tid + 256];
    float ss = v0 * v0 + v1 * v1;
#pragma unroll
    for (int o = 16; o; o >>= 1) ss += __shfl_xor_sync(0xffffffffu, ss, o);
    __shared__ float red[8];
    if ((tid & 31) == 0) red[tid >> 5] = ss;
    __syncthreads();
    float tot = red[0] + red[1] + red[2] + red[3] +
                red[4] + red[5] + red[6] + red[7];
    float scale = rsqrtf(tot * (1.f / DMODEL) + 1e-5f);
    out[(size_t)t * DMODEL + tid]       = v0 * scale * w[tid];
    out[(size_t)t * DMODEL + tid + 256] = v1 * scale * w[tid + 256];
}

// ---------------- depthwise causal conv (k=4) + bias + silu -----------------
__global__ __launch_bounds__(256)
void conv_silu_k(const float* __restrict__ xz, const float* __restrict__ cw,
                 const float* __restrict__ cb, float* __restrict__ xi)
{
    const int idx = blockIdx.x * 256 + threadIdx.x;   // t*ED + e
    const int e = idx & (ED - 1);
    const int t = idx >> 10;
    const int l = t & (LSEQ - 1);
    const float* base = xz + (size_t)t * (2 * ED) + e;
    float acc = cb[e];
#pragma unroll
    for (int k = 0; k < DCONV; k++) {
        int ll = l - (DCONV - 1) + k;
        if (ll >= 0)
            acc = fmaf(base[(ptrdiff_t)(k - (DCONV - 1)) * (2 * ED)],
                       cw[e * DCONV + k], acc);
    }
    xi[idx] = silu_f(acc);
}

// ---------------- chunked selective scan -------------------------------------
__global__ __launch_bounds__(256)
void scan_p1(const float* __restrict__ delta, const float* __restrict__ xi,
             const float* __restrict__ dbc, const float* __restrict__ A_log,
             float* __restrict__ Pa, float* __restrict__ Qa)
{
    const int tid = threadIdx.x;
    const int j   = blockIdx.x >> 7;
    const int cb  = blockIdx.x & 127;
    const int cl  = tid >> 4;
    const int n   = tid & 15;
    const int c   = cb * 16 + cl;
    const int b   = c >> 10;
    const int e   = c & (ED - 1);

    const float a = -__expf(A_log[e * DSTATE + n]);
    const size_t t0 = (size_t)b * LSEQ + (size_t)j * CL;
    const float* dp = delta + t0 * ED + e;
    const float* xp = xi    + t0 * ED + e;
    const float* bp = dbc   + t0 * 64 + DTRANK + n;

    float P = 1.f, q = 0.f;
#pragma unroll 4
    for (int l = 0; l < CL; l++) {
        float dv = dp[(size_t)l * ED];
        float xv = xp[(size_t)l * ED];
        float Bv = bp[(size_t)l * 64];
        float dA = __expf(dv * a);
        P *= dA;
        q = fmaf(dA, q, dv * xv * Bv);
    }
    const int o = (c * NC + j) * DSTATE + n;
    Pa[o] = P;
    Qa[o] = q;
}

__global__ __launch_bounds__(256)
void scan_p2(const float* __restrict__ Pa, const float* __restrict__ Qa,
             float* __restrict__ S0)
{
    const int gid = blockIdx.x * 256 + threadIdx.x;
    const int c = gid >> 4;
    const int n = gid & 15;
    const int base = c * NC * DSTATE + n;
    float s = 0.f;
#pragma unroll
    for (int jj = 0; jj < NC; jj++) {
        S0[base + jj * DSTATE] = s;
        s = fmaf(Pa[base + jj * DSTATE], s, Qa[base + jj * DSTATE]);
    }
}

__global__ __launch_bounds__(256)
void scan_p3(const float* __restrict__ delta, const float* __restrict__ xi,
             const float* __restrict__ xz, const float* __restrict__ dbc,
             const float* __restrict__ A_log, const float* __restrict__ Dp,
             const float* __restrict__ S0, float* __restrict__ y)
{
    const int tid = threadIdx.x;
    const int j   = blockIdx.x >> 7;
    const int cb  = blockIdx.x & 127;
    const int cl  = tid >> 4;
    const int n   = tid & 15;
    const int c   = cb * 16 + cl;
    const int b   = c >> 10;
    const int e   = c & (ED - 1);

    const float a  = -__expf(A_log[e * DSTATE + n]);
    const float dE = Dp[e];
    const size_t t0 = (size_t)b * LSEQ + (size_t)j * CL;
    const float* dp = delta + t0 * ED + e;
    const float* xp = xi    + t0 * ED + e;
    const float* zp = xz    + t0 * (2 * ED) + ED + e;
    const float* bp = dbc   + t0 * 64 + DTRANK + n;
    const float* cp = dbc   + t0 * 64 + DTRANK + DSTATE + n;
    float*       yp = y     + t0 * ED + e;

    float s = S0[(c * NC + j) * DSTATE + n];
#pragma unroll 4
    for (int l = 0; l < CL; l++) {
        float dv = dp[(size_t)l * ED];
        float xv = xp[(size_t)l * ED];
        float Bv = bp[(size_t)l * 64];
        float Cv = cp[(size_t)l * 64];
        float dA = __expf(dv * a);
        s = fmaf(dA, s, dv * xv * Bv);
        float p = s * Cv;
        p += __shfl_xor_sync(0xffffffffu, p, 8, 16);
        p += __shfl_xor_sync(0xffffffffu, p, 4, 16);
        p += __shfl_xor_sync(0xffffffffu, p, 2, 16);
        p += __shfl_xor_sync(0xffffffffu, p, 1, 16);
        if (n == 0) {
            float zv = zp[(size_t)l * (2 * ED)];
            yp[(size_t)l * ED] = (p + dE * xv) * silu_f(zv);
        }
    }
}

// ---------------- launcher ----------------------------------------------------
// dynamic smem sizes per instantiation
#define SMB(BM,BN,BK) (2*((BM)+(BN))*((BK)+4)*4)

extern "C" void kernel_launch(void* const* d_in, const int* in_sizes, int n_in,
                              void* d_out, int out_size)
{
    (void)in_sizes; (void)n_in; (void)out_size;
    const float* x      = (const float*)d_in[0];
    const float* emb_w  = (const float*)d_in[1];
    const float* emb_b  = (const float*)d_in[2];
    const float* in_w   = (const float*)d_in[3];
    const float* conv_w = (const float*)d_in[4];
    const float* conv_b = (const float*)d_in[5];
    const float* xp_w   = (const float*)d_in[6];
    const float* dt_w   = (const float*)d_in[7];
    const float* dt_b   = (const float*)d_in[8];
    const float* A_log  = (const float*)d_in[9];
    const float* Dparam = (const float*)d_in[10];
    const float* out_w  = (const float*)d_in[11];
    const float* norm_w = (const float*)d_in[12];
    float* out = (float*)d_out;

    float* scratch = nullptr;
    cudaGetSymbolAddress((void**)&scratch, g_scratch);
    float* h     = scratch + OFF_H;
    float* hn    = scratch + OFF_HN;
    float* xz    = scratch + OFF_XZ;
    float* xi    = scratch + OFF_XI;
    float* delta = scratch + OFF_DELTA;
    float* y     = scratch + OFF_Y;
    float* dbc   = scratch + OFF_DBC;
    float* Pa    = scratch + OFF_P;
    float* Qa    = scratch + OFF_Q;
    float* S0    = scratch + OFF_S0;
    float* dbcp  = scratch + OFF_DBCP;

    // opt-in to >48KB dynamic smem (idempotent; no allocation)
    cudaFuncSetAttribute(gemm_tf32<128,128,32,true,false,false>,
        cudaFuncAttributeMaxDynamicSharedMemorySize, SMB(128,128,32));
    cudaFuncSetAttribute(gemm_tf32<128,128,64,false,false,false>,
        cudaFuncAttributeMaxDynamicSharedMemorySize, SMB(128,128,64));
    cudaFuncSetAttribute(gemm_tf32<64,64,64,false,false,false>,
        cudaFuncAttributeMaxDynamicSharedMemorySize, SMB(64,64,64));
    cudaFuncSetAttribute(gemm_tf32<128,128,32,true,true,false>,
        cudaFuncAttributeMaxDynamicSharedMemorySize, SMB(128,128,32));
    cudaFuncSetAttribute(gemm_tf32<128,128,64,false,false,true>,
        cudaFuncAttributeMaxDynamicSharedMemorySize, SMB(128,128,64));

    // h = x @ emb_w^T + emb_b          (M=4096, N=512, K=64)
    gemm_tf32<128,128,32,true,false,false>
        <<<dim3(DMODEL/128, T/128), 256, SMB(128,128,32)>>>(
        x, INPUT_D, emb_w, INPUT_D, emb_b, nullptr, h, DMODEL, INPUT_D, 0);

    for (int i = 0; i < NL; i++) {
        const float* in_w_i   = in_w   + (size_t)i * 2 * ED * DMODEL;
        const float* conv_w_i = conv_w + (size_t)i * ED * DCONV;
        const float* conv_b_i = conv_b + (size_t)i * ED;
        const float* xp_w_i   = xp_w   + (size_t)i * 64 * ED;
        const float* dt_w_i   = dt_w   + (size_t)i * ED * DTRANK;
        const float* dt_b_i   = dt_b   + (size_t)i * ED;
        const float* A_log_i  = A_log  + (size_t)i * ED * DSTATE;
        const float* D_i      = Dparam + (size_t)i * ED;
        const float* out_w_i  = out_w  + (size_t)i * DMODEL * ED;
        const float* norm_w_i = norm_w + (size_t)i * DMODEL;

        // hn = rmsnorm(h)
        rmsnorm_k<<<T, 256>>>(h, norm_w_i, hn);

        // xz = hn @ in_proj_w^T          (M=4096, N=2048, K=512)
        gemm_tf32<128,128,64,false,false,false>
            <<<dim3((2*ED)/128, T/128), 256, SMB(128,128,64)>>>(
            hn, DMODEL, in_w_i, DMODEL, nullptr, nullptr, xz, 2*ED, DMODEL, 0);

        // xi = silu(conv(xz[:, :ED]) + cb)
        conv_silu_k<<<(T*ED)/256, 256>>>(xz, conv_w_i, conv_b_i, xi);

        // dbc = xi @ x_proj_w^T          (M=4096, N=64, K=1024), split-K=4
        gemm_tf32<64,64,64,false,false,false>
            <<<dim3(1, T/64, 4), 256, SMB(64,64,64)>>>(
            xi, ED, xp_w_i, ED, nullptr, nullptr, dbcp, 64, ED/4,
            (size_t)T * 64);
        reduce4_k<<<(T*64)/256, 256>>>(dbcp, dbc);

        // delta = softplus(dbc[:, :32] @ dt_w^T + dt_b)  (M=4096, N=1024, K=32)
        gemm_tf32<128,128,32,true,true,false>
            <<<dim3(ED/128, T/128), 256, SMB(128,128,32)>>>(
            dbc, 64, dt_w_i, DTRANK, dt_b_i, nullptr, delta, ED, DTRANK, 0);

        // chunked selective scan -> y
        scan_p1<<<NC*128, 256>>>(delta, xi, dbc, A_log_i, Pa, Qa);
        scan_p2<<<(NCHAN*DSTATE)/256, 256>>>(Pa, Qa, S0);
        scan_p3<<<NC*128, 256>>>(delta, xi, xz, dbc, A_log_i, D_i, S0, y);

        // dest = h + y @ out_proj_w^T    (M=4096, N=512, K=1024)
        float* dest = (i == NL - 1) ? out : h;
        gemm_tf32<128,128,64,false,false,true>
            <<<dim3(DMODEL/128, T/128), 256, SMB(128,128,64)>>>(
            y, ED, out_w_i, ED, nullptr, h, dest, DMODEL, ED, 0);
    }
}